// round 12
// baseline (speedup 1.0000x reference)
#include <cuda_runtime.h>

#define D_MODEL 512
static constexpr float INT64_MAX_F = 9.2233720368547758e18f;

// ---------------------------------------------------------------------------
// Fused lgamma + digamma for t in [1, ~9] (shift-by-4 asymptotic).
// ---------------------------------------------------------------------------
__device__ __forceinline__ void lgamma_digamma(float t, float& lg, float& dg) {
    const float u = t * (t + 3.0f);
    const float d = u * (u + 2.0f);
    const float y = t + 4.0f;
    const float ln_y  = logf(y);
    const float inv_y = __fdividef(1.0f, y);
    const float inv2  = inv_y * inv_y;
    const float inv_d = __fdividef(1.0f, d);
    const float r    = (2.0f * t + 3.0f) * (2.0f * u + 2.0f) * inv_d;
    const float ln_p = logf(d);

    lg = fmaf(y - 0.5f, ln_y, -y) + 0.918938533204672742f
       + inv_y * (0.0833333333333f - inv2 * (0.00277777777778f - inv2 * 0.000793650793651f))
       - ln_p;
    dg = ln_y - 0.5f * inv_y
       - inv2 * (0.0833333333333f - inv2 * (0.00833333333333f - inv2 * 0.00396825396825f))
       - r;
}

// ---------------------------------------------------------------------------
// Fused pipelined kernel. Each warp grid-strides over actor PAIRS with a
// double-buffered register file: loads for pair k+1 (and its prev values)
// are issued BEFORE consuming pair k, so the epilogue math for pair k runs
// entirely inside the memory shadow of pair k+1's gathers.
// After the butterfly, every lane holds all 4 sums; lanes 0 and 1 each
// complete the full epilogue for one of the pair's two actors.
// ---------------------------------------------------------------------------
struct PairBuf { float4 v[2][4]; float pv; };

__device__ __forceinline__ void issue_pair(const float* __restrict__ x,
                                           const int*   __restrict__ actors,
                                           const int*   __restrict__ prev,
                                           int pair, int lane, PairBuf& b)
{
    const int ia = 2 * pair;
    const float4* xa = reinterpret_cast<const float4*>(x + (size_t)__ldg(actors + ia)     * D_MODEL);
    const float4* xb = reinterpret_cast<const float4*>(x + (size_t)__ldg(actors + ia + 1) * D_MODEL);
    #pragma unroll
    for (int j = 0; j < 4; j++) b.v[0][j] = __ldg(xa + j * 32 + lane);
    #pragma unroll
    for (int j = 0; j < 4; j++) b.v[1][j] = __ldg(xb + j * 32 + lane);
    if (lane < 2) b.pv = (float)__ldg(prev + ia + lane);
}

__device__ __forceinline__ void consume_pair(const PairBuf& bf,
                                             const float4 (&w0r)[4], const float4 (&w1r)[4],
                                             float b0, float b1,
                                             int pair, int lane,
                                             float* __restrict__ out, int n_actors)
{
    float a0 = 0.0f, a1 = 0.0f, c0 = 0.0f, c1 = 0.0f;
    #pragma unroll
    for (int j = 0; j < 4; j++) {
        const float4 va = bf.v[0][j];
        const float4 vb = bf.v[1][j];
        a0 = fmaf(va.x, w0r[j].x, a0); a0 = fmaf(va.y, w0r[j].y, a0);
        a0 = fmaf(va.z, w0r[j].z, a0); a0 = fmaf(va.w, w0r[j].w, a0);
        a1 = fmaf(va.x, w1r[j].x, a1); a1 = fmaf(va.y, w1r[j].y, a1);
        a1 = fmaf(va.z, w1r[j].z, a1); a1 = fmaf(va.w, w1r[j].w, a1);
        c0 = fmaf(vb.x, w0r[j].x, c0); c0 = fmaf(vb.y, w0r[j].y, c0);
        c0 = fmaf(vb.z, w0r[j].z, c0); c0 = fmaf(vb.w, w0r[j].w, c0);
        c1 = fmaf(vb.x, w1r[j].x, c1); c1 = fmaf(vb.y, w1r[j].y, c1);
        c1 = fmaf(vb.z, w1r[j].z, c1); c1 = fmaf(vb.w, w1r[j].w, c1);
    }
    #pragma unroll
    for (int off = 16; off > 0; off >>= 1) {
        a0 += __shfl_xor_sync(0xffffffffu, a0, off);
        a1 += __shfl_xor_sync(0xffffffffu, a1, off);
        c0 += __shfl_xor_sync(0xffffffffu, c0, off);
        c1 += __shfl_xor_sync(0xffffffffu, c1, off);
    }

    // Lanes 0,1: full epilogue for actor 2*pair + lane (no intra-pair
    // divergence: both lanes execute the same instruction sequence).
    if (lane < 2) {
        const float s0 = (lane == 0) ? a0 : c0;
        const float s1 = (lane == 0) ? a1 : c1;
        const int   i  = 2 * pair + lane;

        const float z0 = s0 + b0;
        const float z1 = s1 + b1;
        const float a  = fmaf(z0, z0, 1.0f);
        const float bb = fmaf(z1, z1, 1.0f);

        const float action = bf.pv * (1.0f / INT64_MAX_F);

        float lga, dga, lgb, dgb, lgab, dgab;
        lgamma_digamma(a,      lga,  dga);
        lgamma_digamma(bb,     lgb,  dgb);
        lgamma_digamma(a + bb, lgab, dgab);

        const float lbeta = lga + lgb - lgab;

        const float logprob = (a - 1.0f) * logf(action)
                            + (bb - 1.0f) * log1pf(-action)
                            - lbeta;

        const float ent = lbeta
                        - (a - 1.0f)  * dga
                        - (bb - 1.0f) * dgb
                        + (a + bb - 2.0f) * dgab;

        out[i]                        = action * INT64_MAX_F;
        out[(size_t)n_actors + i]     = logprob;
        out[2 * (size_t)n_actors + i] = ent;
        float2 l; l.x = a; l.y = bb;
        *reinterpret_cast<float2*>(out + 3 * (size_t)n_actors + 2 * (size_t)i) = l;
    }
}

__global__ void __launch_bounds__(256)
cah_fused_kernel(const float* __restrict__ x,
                 const int*   __restrict__ actors,
                 const float* __restrict__ w,
                 const float* __restrict__ bvec,
                 const int*   __restrict__ prev,
                 float*       __restrict__ out,
                 int n_actors)
{
    const int tid    = threadIdx.x;
    const int lane   = tid & 31;
    const int gwarp  = (blockIdx.x * blockDim.x + tid) >> 5;
    const int nwarp  = (gridDim.x * blockDim.x) >> 5;
    const int npairs = n_actors >> 1;   // n_actors even (262144)

    float4 w0r[4], w1r[4];
    #pragma unroll
    for (int j = 0; j < 4; j++) {
        int c = j * 128 + lane * 4;
        w0r[j] = *reinterpret_cast<const float4*>(w + c);
        w1r[j] = *reinterpret_cast<const float4*>(w + D_MODEL + c);
    }
    const float b0 = bvec[0];
    const float b1 = bvec[1];

    int p0 = gwarp;
    if (p0 >= npairs) return;

    PairBuf A, B;
    issue_pair(x, actors, prev, p0, lane, A);

    for (;;) {
        const int p1 = p0 + nwarp;
        if (p1 < npairs) issue_pair(x, actors, prev, p1, lane, B);
        consume_pair(A, w0r, w1r, b0, b1, p0, lane, out, n_actors);
        if (p1 >= npairs) return;

        const int p2 = p1 + nwarp;
        if (p2 < npairs) issue_pair(x, actors, prev, p2, lane, A);
        consume_pair(B, w0r, w1r, b0, b1, p1, lane, out, n_actors);
        if (p2 >= npairs) return;

        p0 = p2;
    }
}

extern "C" void kernel_launch(void* const* d_in, const int* in_sizes, int n_in,
                              void* d_out, int out_size)
{
    const float* x      = (const float*)d_in[0];
    const int*   actors = (const int*)  d_in[1];
    const float* w      = (const float*)d_in[2];
    const float* bvec   = (const float*)d_in[3];
    const int*   prev   = (const int*)  d_in[4];
    float*       out    = (float*)d_out;

    const int n_actors = in_sizes[1];  // 262144

    // 2048 CTAs = 16384 warps -> 8 pairs per warp, double-buffered & fused.
    cah_fused_kernel<<<2048, 256>>>(x, actors, w, bvec, prev, out, n_actors);
}

// round 13
// speedup vs baseline: 1.2316x; 1.2316x over previous
#include <cuda_runtime.h>

#define D_MODEL 512
static constexpr float INT64_MAX_F = 9.2233720368547758e18f;

// ---------------------------------------------------------------------------
// Shifted-Stirling pieces for t in [1, ~9]:
//   y = t + 4, u = t(t+3), d = t(t+1)(t+2)(t+3) = u(u+2)
//   lgamma(t) = stirling(y) - ln d        (ln d returned via d, merged later)
//   digamma(t) = psi(y) - (2t+3)(2u+2)/d
// Returns st = stirling(y), dg = digamma(t), d = recurrence product.
// ---------------------------------------------------------------------------
__device__ __forceinline__ void lgd_parts(float t, float& st, float& dg, float& d) {
    const float u = t * (t + 3.0f);
    d = u * (u + 2.0f);
    const float y = t + 4.0f;
    const float ln_y  = logf(y);
    const float inv_y = __fdividef(1.0f, y);
    const float inv2  = inv_y * inv_y;
    const float r     = (2.0f * t + 3.0f) * (2.0f * u + 2.0f) * __fdividef(1.0f, d);

    st = fmaf(y - 0.5f, ln_y, -y) + 0.918938533204672742f   // 0.5*ln(2*pi)
       + inv_y * (0.0833333333333f - inv2 * (0.00277777777778f - inv2 * 0.000793650793651f));
    dg = ln_y - 0.5f * inv_y
       - inv2 * (0.0833333333333f - inv2 * (0.00833333333333f - inv2 * 0.00396825396825f))
       - r;
}

// ---------------------------------------------------------------------------
// Kernel A: gather + dual dot product (proven best configuration, unchanged).
// One warp handles 4 actors; 16 independent float4 gathers per lane.
// ---------------------------------------------------------------------------
__global__ void __launch_bounds__(256)
cah_gemv_kernel(const float* __restrict__ x,
                const int*   __restrict__ actors,
                const float* __restrict__ w,
                const float* __restrict__ bvec,
                float*       __restrict__ out,
                int n_actors)
{
    const int lane = threadIdx.x & 31;
    const int warp = (blockIdx.x * blockDim.x + threadIdx.x) >> 5;

    const int i0 = warp * 4;
    if (i0 >= n_actors) return;

    float4 w0r[4], w1r[4];
    #pragma unroll
    for (int j = 0; j < 4; j++) {
        int c = j * 128 + lane * 4;
        w0r[j] = *reinterpret_cast<const float4*>(w + c);
        w1r[j] = *reinterpret_cast<const float4*>(w + D_MODEL + c);
    }
    const float b0 = bvec[0];
    const float b1 = bvec[1];

    const float4* xr[4];
    #pragma unroll
    for (int q = 0; q < 4; q++) {
        const int idx = (i0 + q < n_actors) ? (i0 + q) : i0;
        const int row = __ldg(actors + idx);
        xr[q] = reinterpret_cast<const float4*>(x + (size_t)row * D_MODEL);
    }

    float4 v[4][4];
    #pragma unroll
    for (int q = 0; q < 4; q++)
        #pragma unroll
        for (int j = 0; j < 4; j++)
            v[q][j] = __ldg(xr[q] + j * 32 + lane);

    float acc[4][2];
    #pragma unroll
    for (int q = 0; q < 4; q++) {
        float s0 = 0.0f, s1 = 0.0f;
        #pragma unroll
        for (int j = 0; j < 4; j++) {
            s0 = fmaf(v[q][j].x, w0r[j].x, s0); s0 = fmaf(v[q][j].y, w0r[j].y, s0);
            s0 = fmaf(v[q][j].z, w0r[j].z, s0); s0 = fmaf(v[q][j].w, w0r[j].w, s0);
            s1 = fmaf(v[q][j].x, w1r[j].x, s1); s1 = fmaf(v[q][j].y, w1r[j].y, s1);
            s1 = fmaf(v[q][j].z, w1r[j].z, s1); s1 = fmaf(v[q][j].w, w1r[j].w, s1);
        }
        acc[q][0] = s0; acc[q][1] = s1;
    }

    #pragma unroll
    for (int off = 16; off > 0; off >>= 1) {
        #pragma unroll
        for (int q = 0; q < 4; q++) {
            acc[q][0] += __shfl_xor_sync(0xffffffffu, acc[q][0], off);
            acc[q][1] += __shfl_xor_sync(0xffffffffu, acc[q][1], off);
        }
    }

    if (lane == 0) {
        float lg[8];
        #pragma unroll
        for (int q = 0; q < 4; q++) {
            const float z0 = acc[q][0] + b0;
            const float z1 = acc[q][1] + b1;
            lg[2*q]   = fmaf(z0, z0, 1.0f);
            lg[2*q+1] = fmaf(z1, z1, 1.0f);
        }
        float* lbase = out + 3 * (size_t)n_actors + 2 * (size_t)i0;
        if (i0 + 3 < n_actors) {
            *reinterpret_cast<float4*>(lbase)     = make_float4(lg[0], lg[1], lg[2], lg[3]);
            *reinterpret_cast<float4*>(lbase + 4) = make_float4(lg[4], lg[5], lg[6], lg[7]);
        } else {
            for (int q = 0; q < 4 && i0 + q < n_actors; q++) {
                lbase[2*q]   = lg[2*q];
                lbase[2*q+1] = lg[2*q+1];
            }
        }
    }
}

// ---------------------------------------------------------------------------
// Kernel B: slimmed epilogue. One thread per actor.
//   - log1pf(-action) == -action exactly at fp32 (action <= 2.4e-10)
//   - the three recurrence-product logs merge into ONE logf:
//       lbeta = st_a + st_b - st_ab - ln(d_a*d_b/d_ab)
// ---------------------------------------------------------------------------
__global__ void __launch_bounds__(256)
cah_epilogue_kernel(const int* __restrict__ prev,
                    float*     __restrict__ out,
                    int n_actors)
{
    const int i = blockIdx.x * blockDim.x + threadIdx.x;
    if (i >= n_actors) return;

    const float2 l = *reinterpret_cast<const float2*>(out + 3 * (size_t)n_actors + 2 * (size_t)i);
    const float a  = l.x;
    const float bb = l.y;

    const float pa     = (float)__ldg(prev + i);
    const float action = pa * (1.0f / INT64_MAX_F);

    float st_a, dg_a, d_a;
    float st_b, dg_b, d_b;
    float st_s, dg_s, d_s;
    lgd_parts(a,      st_a, dg_a, d_a);
    lgd_parts(bb,     st_b, dg_b, d_b);
    lgd_parts(a + bb, st_s, dg_s, d_s);

    // merged recurrence-product log
    const float lbeta = st_a + st_b - st_s
                      - logf(d_a * d_b * __fdividef(1.0f, d_s));

    const float logprob = (a - 1.0f) * logf(action)
                        - (bb - 1.0f) * action       // == (bb-1)*log1p(-action)
                        - lbeta;

    const float ent = lbeta
                    - (a - 1.0f)  * dg_a
                    - (bb - 1.0f) * dg_b
                    + (a + bb - 2.0f) * dg_s;

    out[i]                        = action * INT64_MAX_F;
    out[(size_t)n_actors + i]     = logprob;
    out[2 * (size_t)n_actors + i] = ent;
}

extern "C" void kernel_launch(void* const* d_in, const int* in_sizes, int n_in,
                              void* d_out, int out_size)
{
    const float* x      = (const float*)d_in[0];
    const int*   actors = (const int*)  d_in[1];
    const float* w      = (const float*)d_in[2];
    const float* bvec   = (const float*)d_in[3];
    const int*   prev   = (const int*)  d_in[4];
    float*       out    = (float*)d_out;

    const int n_actors = in_sizes[1];  // 262144

    const int T = 256;

    const int warpsA  = (n_actors + 3) / 4;
    const int blocksA = (warpsA * 32 + T - 1) / T;
    cah_gemv_kernel<<<blocksA, T>>>(x, actors, w, bvec, out, n_actors);

    const int blocksB = (n_actors + T - 1) / T;
    cah_epilogue_kernel<<<blocksB, T>>>(prev, out, n_actors);
}